// round 6
// baseline (speedup 1.0000x reference)
#include <cuda_runtime.h>

#define N_NODES 50000
#define N_EDGES 800000
#define N_GRAPHS 256
#define HID 128
#define BN_EPS 1e-5f

// ---------------- device scratch (no allocations allowed) ----------------
__device__ float g_agg[N_NODES * HID];        // (1+eps)*h + segment_sum
__device__ float g_x1[N_NODES * HID];         // output of first linear (pre-BN)
__device__ float g_h[N_NODES * HID];          // layer-0 output h
__device__ float g_hcat[N_NODES * 2 * HID];   // concat of both encoders
__device__ float g_stats[2 * HID];            // col sums / col sumsq
__device__ float g_scale[HID];                // BN fused scale
__device__ float g_shift[HID];                // BN fused shift
__device__ float g_hg[N_GRAPHS * 2 * HID];    // per-graph readout
__device__ float g_m1[N_GRAPHS * HID];
__device__ float g_m2[N_GRAPHS * HID];

// ---------------- f32x2 packed-FMA helpers (sm_100+) ----------------
static __device__ __forceinline__ unsigned long long pack2(float lo, float hi) {
    unsigned long long r;
    asm("mov.b64 %0, {%1, %2};" : "=l"(r) : "f"(lo), "f"(hi));
    return r;
}
static __device__ __forceinline__ void unpack2(unsigned long long v, float &lo, float &hi) {
    asm("mov.b64 {%0, %1}, %2;" : "=f"(lo), "=f"(hi) : "l"(v));
}
static __device__ __forceinline__ unsigned long long ffma2(
    unsigned long long a, unsigned long long b, unsigned long long c) {
    unsigned long long d;
    asm("fma.rn.f32x2 %0, %1, %2, %3;" : "=l"(d) : "l"(a), "l"(b), "l"(c));
    return d;
}

static __device__ __forceinline__ void red_add_v4(float *p, float4 v) {
    asm volatile("red.global.add.v4.f32 [%0], {%1, %2, %3, %4};"
                 :: "l"(p), "f"(v.x), "f"(v.y), "f"(v.z), "f"(v.w)
                 : "memory");
}

// ---------------- kernels ----------------

// agg[i] = (1+eps)*h[i]; also zero the BN stats accumulators.
__global__ void init_agg_kernel(const float *__restrict__ hin,
                                const float *__restrict__ eps, int eidx) {
    float e1 = 1.0f + __ldg(eps + eidx);
    int idx = blockIdx.x * blockDim.x + threadIdx.x;  // float4 index, exact grid
    float4 v = __ldg((const float4 *)hin + idx);
    v.x *= e1; v.y *= e1; v.z *= e1; v.w *= e1;
    ((float4 *)g_agg)[idx] = v;
    if (blockIdx.x == 0 && threadIdx.x < 2 * HID) g_stats[threadIdx.x] = 0.0f;
}

// For each edge: agg[dst] += h[src]. 32 lanes/edge, float4 per lane, vector REDG.
__global__ void scatter_kernel(const float *__restrict__ hin,
                               const int *__restrict__ src,
                               const int *__restrict__ dst) {
    int e = blockIdx.x * 8 + (threadIdx.x >> 5);
    int lane = threadIdx.x & 31;
    if (e >= N_EDGES) return;
    int s = __ldg(src + e);
    int d = __ldg(dst + e);
    float4 v = __ldg((const float4 *)(hin + (size_t)s * HID) + lane);
    red_add_v4(g_agg + (size_t)d * HID + lane * 4, v);
}

// GEMM: out[M x 128] = f(A)[M x 128] @ W[128 x 128] + bias
//  - apply_bn: A is transformed elementwise relu(a*scale[k]+shift[k]) at load
//  - do_stats: accumulate column sum/sumsq of (acc+bias) into g_stats
//  - relu_out: relu on output
// Tile: 64 rows x 128 cols per block, 256 threads, each thread 8 rows x 4 cols.
// Accumulation via packed fma.rn.f32x2 (2 FMA lanes/instr).
__global__ void __launch_bounds__(256) gemm_kernel(
    const float *__restrict__ A, const float *__restrict__ W,
    const float *__restrict__ bias, float *__restrict__ out,
    int ostride, int ocol, int apply_bn, int relu_out, int do_stats) {
    __shared__ float Ash[64 * 64];    // 16 KB
    __shared__ float Wsh[64 * 128];   // 32 KB
    int tid = threadIdx.x;
    int tx = tid & 31;        // 32 col-groups of 4 cols
    int ty = tid >> 5;        // 8 row-groups of 8 rows
    int rowBase = blockIdx.x * 64;

    unsigned long long acc01[8], acc23[8];
    unsigned long long zz = pack2(0.0f, 0.0f);
#pragma unroll
    for (int r = 0; r < 8; r++) { acc01[r] = zz; acc23[r] = zz; }

    for (int kk = 0; kk < HID; kk += 64) {
        // ---- load A tile (64 rows x 64 k), fused BN+ReLU if requested ----
#pragma unroll
        for (int i = tid; i < 1024; i += 256) {  // 1024 float4s
            int ar = i >> 4, ac4 = i & 15;
            int grow = rowBase + ar;
            float4 v = make_float4(0.0f, 0.0f, 0.0f, 0.0f);
            if (grow < N_NODES)
                v = __ldg((const float4 *)(A + (size_t)grow * HID + kk) + ac4);
            if (apply_bn) {
                int c = kk + ac4 * 4;
                v.x = fmaxf(v.x * g_scale[c + 0] + g_shift[c + 0], 0.0f);
                v.y = fmaxf(v.y * g_scale[c + 1] + g_shift[c + 1], 0.0f);
                v.z = fmaxf(v.z * g_scale[c + 2] + g_shift[c + 2], 0.0f);
                v.w = fmaxf(v.w * g_scale[c + 3] + g_shift[c + 3], 0.0f);
            }
            *(float4 *)&Ash[ar * 64 + ac4 * 4] = v;
        }
        // ---- load W tile (64 k x 128 cols) ----
#pragma unroll
        for (int i = tid; i < 2048; i += 256) {  // 2048 float4s
            int wr = i >> 5, wc4 = i & 31;
            *(float4 *)&Wsh[wr * 128 + wc4 * 4] =
                __ldg((const float4 *)(W + (size_t)(kk + wr) * HID) + wc4);
        }
        __syncthreads();
        // ---- compute ----
#pragma unroll 4
        for (int k4 = 0; k4 < 64; k4 += 4) {
            float4 av[8];
#pragma unroll
            for (int r = 0; r < 8; r++)
                av[r] = *(const float4 *)&Ash[(ty * 8 + r) * 64 + k4];
#pragma unroll
            for (int k2 = 0; k2 < 4; k2++) {
                float4 w = *(const float4 *)&Wsh[(k4 + k2) * 128 + tx * 4];
                unsigned long long w01 = pack2(w.x, w.y);
                unsigned long long w23 = pack2(w.z, w.w);
#pragma unroll
                for (int r = 0; r < 8; r++) {
                    float a = (k2 == 0) ? av[r].x : (k2 == 1) ? av[r].y
                              : (k2 == 2) ? av[r].z : av[r].w;
                    unsigned long long aa = pack2(a, a);
                    acc01[r] = ffma2(aa, w01, acc01[r]);
                    acc23[r] = ffma2(aa, w23, acc23[r]);
                }
            }
        }
        __syncthreads();
    }

    // ---- epilogue ----
    int c0 = tx * 4;
    float b0 = __ldg(bias + c0 + 0), b1 = __ldg(bias + c0 + 1);
    float b2 = __ldg(bias + c0 + 2), b3 = __ldg(bias + c0 + 3);
    float s0 = 0, s1 = 0, s2 = 0, s3 = 0;
    float q0 = 0, q1 = 0, q2 = 0, q3 = 0;
#pragma unroll
    for (int r = 0; r < 8; r++) {
        int grow = rowBase + ty * 8 + r;
        if (grow < N_NODES) {
            float y0, y1, y2, y3;
            unpack2(acc01[r], y0, y1);
            unpack2(acc23[r], y2, y3);
            y0 += b0; y1 += b1; y2 += b2; y3 += b3;
            if (relu_out) {
                y0 = fmaxf(y0, 0.0f); y1 = fmaxf(y1, 0.0f);
                y2 = fmaxf(y2, 0.0f); y3 = fmaxf(y3, 0.0f);
            }
            *(float4 *)(out + (size_t)grow * ostride + ocol + c0) =
                make_float4(y0, y1, y2, y3);
            if (do_stats) {
                s0 += y0; s1 += y1; s2 += y2; s3 += y3;
                q0 += y0 * y0; q1 += y1 * y1; q2 += y2 * y2; q3 += y3 * y3;
            }
        }
    }
    if (do_stats) {
        float *sred = Ash;  // reuse: [0..127]=sum, [128..255]=sumsq
        sred[tid] = 0.0f;   // tid < 256 covers all 256 slots
        __syncthreads();
        atomicAdd(&sred[c0 + 0], s0); atomicAdd(&sred[c0 + 1], s1);
        atomicAdd(&sred[c0 + 2], s2); atomicAdd(&sred[c0 + 3], s3);
        atomicAdd(&sred[128 + c0 + 0], q0); atomicAdd(&sred[128 + c0 + 1], q1);
        atomicAdd(&sred[128 + c0 + 2], q2); atomicAdd(&sred[128 + c0 + 3], q3);
        __syncthreads();
        atomicAdd(&g_stats[tid], sred[tid]);
    }
}

__global__ void bn_finalize_kernel(const float *__restrict__ gamma,
                                   const float *__restrict__ beta) {
    int c = threadIdx.x;  // 128 threads
    float inv = 1.0f / (float)N_NODES;
    float mu = g_stats[c] * inv;
    float var = g_stats[HID + c] * inv - mu * mu;
    float rs = rsqrtf(var + BN_EPS);
    float sc = rs * __ldg(gamma + c);
    g_scale[c] = sc;
    g_shift[c] = __ldg(beta + c) - mu * sc;
}

__global__ void zero_hg_kernel() {
    int i = blockIdx.x * 256 + threadIdx.x;  // 16384 float4s exactly
    ((float4 *)g_hg)[i] = make_float4(0.0f, 0.0f, 0.0f, 0.0f);
}

// hg[graph_ids[n]] += hcat[n]; 64 lanes/node, float4 per lane.
__global__ void readout_kernel(const int *__restrict__ gid) {
    int node = blockIdx.x * 4 + (threadIdx.x >> 6);
    int lane = threadIdx.x & 63;
    if (node >= N_NODES) return;
    int g = __ldg(gid + node);
    float4 v = __ldg((const float4 *)(g_hcat + (size_t)node * 2 * HID) + lane);
    red_add_v4(g_hg + (size_t)g * 2 * HID + lane * 4, v);
}

// Y[g, t] = act(sum_k X[g,k] * W[k,t] + b[t]); one block per graph row.
__global__ void mlp_kernel(const float *__restrict__ X, int K,
                           const float *__restrict__ W,
                           const float *__restrict__ b,
                           float *__restrict__ Y, int relu) {
    __shared__ float row[256];
    int g = blockIdx.x, t = threadIdx.x;  // 128 threads
    for (int k = t; k < K; k += 128) row[k] = __ldg(X + (size_t)g * K + k);
    __syncthreads();
    float acc = 0.0f;
#pragma unroll 8
    for (int k = 0; k < K; k++) acc = fmaf(row[k], __ldg(W + (size_t)k * HID + t), acc);
    acc += __ldg(b + t);
    if (relu) acc = fmaxf(acc, 0.0f);
    Y[(size_t)g * HID + t] = acc;
}

// out[g] = dot(m2[g], W3) + b3; one block, thread = graph.
__global__ void mlp_out_kernel(const float *__restrict__ W3,
                               const float *__restrict__ b3,
                               float *__restrict__ out) {
    __shared__ float w[HID];
    int t = threadIdx.x;  // 256 threads
    if (t < HID) w[t] = __ldg(W3 + t);
    __syncthreads();
    float acc = 0.0f;
#pragma unroll 8
    for (int k = 0; k < HID; k++) acc = fmaf(g_m2[(size_t)t * HID + k], w[k], acc);
    out[t] = acc + __ldg(b3);
}

// ---------------- launch ----------------
extern "C" void kernel_launch(void *const *d_in, const int *in_sizes, int n_in,
                              void *d_out, int out_size) {
    const float *feats = (const float *)d_in[0];
    const int *src = (const int *)d_in[1];
    const int *dst = (const int *)d_in[2];
    const int *gid = (const int *)d_in[3];
    // d_in[4] is either the scalar n_graphs (size 1) or eps (size 4)
    int base = (in_sizes[4] == 4) ? 4 : 5;
    const float *eps = (const float *)d_in[base + 0];
    const float *Wa  = (const float *)d_in[base + 1];
    const float *ba  = (const float *)d_in[base + 2];
    const float *bng = (const float *)d_in[base + 3];
    const float *bnb = (const float *)d_in[base + 4];
    const float *Wb  = (const float *)d_in[base + 5];
    const float *bb  = (const float *)d_in[base + 6];
    const float *oW1 = (const float *)d_in[base + 7];
    const float *ob1 = (const float *)d_in[base + 8];
    const float *oW2 = (const float *)d_in[base + 9];
    const float *ob2 = (const float *)d_in[base + 10];
    const float *oW3 = (const float *)d_in[base + 11];
    const float *ob3 = (const float *)d_in[base + 12];
    float *out = (float *)d_out;

    void *p;
    cudaGetSymbolAddress(&p, g_agg);  float *agg  = (float *)p;
    cudaGetSymbolAddress(&p, g_x1);   float *x1   = (float *)p;
    cudaGetSymbolAddress(&p, g_h);    float *h    = (float *)p;
    cudaGetSymbolAddress(&p, g_hcat); float *hcat = (float *)p;
    cudaGetSymbolAddress(&p, g_hg);   float *hg   = (float *)p;
    cudaGetSymbolAddress(&p, g_m1);   float *m1   = (float *)p;
    cudaGetSymbolAddress(&p, g_m2);   float *m2   = (float *)p;

    const int GEMM_BLOCKS = (N_NODES + 63) / 64;       // 782
    const int INIT_BLOCKS = (N_NODES * HID / 4) / 256; // 6250 (exact)
    const int SCAT_BLOCKS = N_EDGES / 8;               // 100000 (exact)

    for (int e = 0; e < 2; e++) {
        const float *hin = feats;
        for (int l = 0; l < 2; l++) {
            int idx = e * 2 + l;
            init_agg_kernel<<<INIT_BLOCKS, 256>>>(hin, eps, idx);
            scatter_kernel<<<SCAT_BLOCKS, 256>>>(hin, src + e * N_EDGES,
                                                 dst + e * N_EDGES);
            // x1 = agg @ Wa + ba, with column stats
            gemm_kernel<<<GEMM_BLOCKS, 256>>>(agg, Wa + (size_t)idx * HID * HID,
                                              ba + idx * HID, x1, HID, 0,
                                              /*bn*/0, /*relu*/0, /*stats*/1);
            bn_finalize_kernel<<<1, HID>>>(bng + idx * HID, bnb + idx * HID);
            // h_next = relu?( relu(BN(x1)) @ Wb + bb )
            if (l == 0) {
                gemm_kernel<<<GEMM_BLOCKS, 256>>>(x1, Wb + (size_t)idx * HID * HID,
                                                  bb + idx * HID, h, HID, 0,
                                                  /*bn*/1, /*relu*/1, /*stats*/0);
            } else {
                gemm_kernel<<<GEMM_BLOCKS, 256>>>(x1, Wb + (size_t)idx * HID * HID,
                                                  bb + idx * HID, hcat, 2 * HID,
                                                  e * HID,
                                                  /*bn*/1, /*relu*/0, /*stats*/0);
            }
            hin = h;
        }
    }

    zero_hg_kernel<<<64, 256>>>();
    readout_kernel<<<(N_NODES + 3) / 4, 256>>>(gid);
    mlp_kernel<<<N_GRAPHS, HID>>>(hg, 2 * HID, oW1, ob1, m1, 1);
    mlp_kernel<<<N_GRAPHS, HID>>>(m1, HID, oW2, ob2, m2, 1);
    mlp_out_kernel<<<1, N_GRAPHS>>>(oW3, ob3, out);
}

// round 11
// speedup vs baseline: 1.2259x; 1.2259x over previous
#include <cuda_runtime.h>

#define N_NODES 50000
#define N_EDGES 800000
#define N_GRAPHS 256
#define HID 128
#define BN_EPS 1e-5f

// ---------------- device scratch (no allocations allowed) ----------------
__device__ float g_agg[N_NODES * HID];        // (1+eps)*h + segment_sum
__device__ float g_x1[N_NODES * HID];         // output of first linear (pre-BN)
__device__ float g_h[N_NODES * HID];          // layer-0 output h
__device__ float g_hcat[N_NODES * 2 * HID];   // concat of both encoders
__device__ float g_stats[2 * HID];            // col sums / col sumsq
__device__ float g_scale[HID];                // BN fused scale
__device__ float g_shift[HID];                // BN fused shift
__device__ float g_hg[N_GRAPHS * 2 * HID];    // per-graph readout
__device__ float g_m1[N_GRAPHS * HID];
__device__ float g_m2[N_GRAPHS * HID];
// CSR scratch (dst-sorted adjacency, built per edge type)
__device__ int g_deg[N_NODES];
__device__ int g_ptr[2][N_NODES + 1];
__device__ int g_cursor[N_NODES];
__device__ int g_csrc[2][N_EDGES];

// ---------------- f32x2 packed-FMA helpers (sm_100+) ----------------
static __device__ __forceinline__ unsigned long long pack2(float lo, float hi) {
    unsigned long long r;
    asm("mov.b64 %0, {%1, %2};" : "=l"(r) : "f"(lo), "f"(hi));
    return r;
}
static __device__ __forceinline__ void unpack2(unsigned long long v, float &lo, float &hi) {
    asm("mov.b64 {%0, %1}, %2;" : "=f"(lo), "=f"(hi) : "l"(v));
}
static __device__ __forceinline__ unsigned long long ffma2(
    unsigned long long a, unsigned long long b, unsigned long long c) {
    unsigned long long d;
    asm("fma.rn.f32x2 %0, %1, %2, %3;" : "=l"(d) : "l"(a), "l"(b), "l"(c));
    return d;
}

// ---------------- CSR construction (kernel-launch-only, no memset API) ----------------

__global__ void zero_deg_kernel() {
    int i = blockIdx.x * 256 + threadIdx.x;  // grid covers >= N_NODES
    if (i < N_NODES) g_deg[i] = 0;
}

__global__ void hist_kernel(const int *__restrict__ dst) {
    int e = blockIdx.x * 256 + threadIdx.x;  // exact grid: 3125 x 256
    atomicAdd(&g_deg[__ldg(dst + e)], 1);
}

// Single-block exclusive scan of g_deg into ptr (and cursor copy).
__global__ void scan_kernel(int *__restrict__ ptr, int *__restrict__ cursor) {
    __shared__ int wsum[32];
    __shared__ int carry_s;
    int tid = threadIdx.x, lane = tid & 31, wid = tid >> 5;
    if (tid == 0) carry_s = 0;
    __syncthreads();
    const int TILES = (N_NODES + 1023) / 1024;
    for (int tile = 0; tile < TILES; tile++) {
        int i = tile * 1024 + tid;
        int v = (i < N_NODES) ? g_deg[i] : 0;
        int x = v;
#pragma unroll
        for (int off = 1; off < 32; off <<= 1) {
            int t = __shfl_up_sync(0xffffffffu, x, off);
            if (lane >= off) x += t;
        }
        if (lane == 31) wsum[wid] = x;
        __syncthreads();
        if (wid == 0) {
            int w = wsum[lane];
#pragma unroll
            for (int off = 1; off < 32; off <<= 1) {
                int t = __shfl_up_sync(0xffffffffu, w, off);
                if (lane >= off) w += t;
            }
            wsum[lane] = w;
        }
        __syncthreads();
        int wbase = (wid > 0) ? wsum[wid - 1] : 0;
        int incl = x + wbase + carry_s;
        int excl = incl - v;
        if (i < N_NODES) { ptr[i] = excl; cursor[i] = excl; }
        if (i == N_NODES - 1) ptr[N_NODES] = incl;
        __syncthreads();
        if (tid == 1023) carry_s = incl;
        __syncthreads();
    }
}

__global__ void reorder_kernel(const int *__restrict__ src,
                               const int *__restrict__ dst,
                               int *__restrict__ csrc) {
    int e = blockIdx.x * 256 + threadIdx.x;  // exact grid
    int d = __ldg(dst + e);
    int pos = atomicAdd(&g_cursor[d], 1);
    csrc[pos] = __ldg(src + e);
}

// ---------------- aggregation: agg[n] = (1+eps)*h[n] + sum_{e: dst=n} h[src[e]]
// One warp per node; lane holds 4 columns (float4). Source indices batched
// 32/iteration via one coalesced load + shuffle broadcast.
__global__ void __launch_bounds__(256) gather_agg_kernel(
    const float *__restrict__ hin, const int *__restrict__ ptr,
    const int *__restrict__ csrc, const float *__restrict__ eps, int eidx) {
    if (blockIdx.x == 0 && threadIdx.x < 2 * HID) g_stats[threadIdx.x] = 0.0f;
    int node = (blockIdx.x * 256 + threadIdx.x) >> 5;  // exact: 6250*8 = 50000
    int lane = threadIdx.x & 31;
    float e1 = 1.0f + __ldg(eps + eidx);
    float4 acc = __ldg((const float4 *)(hin + (size_t)node * HID) + lane);
    acc.x *= e1; acc.y *= e1; acc.z *= e1; acc.w *= e1;
    int beg = __ldg(ptr + node), end = __ldg(ptr + node + 1);
    for (int base = beg; base < end; base += 32) {
        int sidx = (base + lane < end) ? __ldg(csrc + base + lane) : 0;
        int m = min(32, end - base);
#pragma unroll 4
        for (int j = 0; j < m; j++) {
            int s = __shfl_sync(0xffffffffu, sidx, j);
            float4 v = __ldg((const float4 *)(hin + (size_t)s * HID) + lane);
            acc.x += v.x; acc.y += v.y; acc.z += v.z; acc.w += v.w;
        }
    }
    ((float4 *)(g_agg + (size_t)node * HID))[lane] = acc;
}

// ---------------- GEMM ----------------
__global__ void __launch_bounds__(256) gemm_kernel(
    const float *__restrict__ A, const float *__restrict__ W,
    const float *__restrict__ bias, float *__restrict__ out,
    int ostride, int ocol, int apply_bn, int relu_out, int do_stats) {
    __shared__ float Ash[64 * 64];
    __shared__ float Wsh[64 * 128];
    int tid = threadIdx.x;
    int tx = tid & 31;
    int ty = tid >> 5;
    int rowBase = blockIdx.x * 64;

    unsigned long long acc01[8], acc23[8];
    unsigned long long zz = pack2(0.0f, 0.0f);
#pragma unroll
    for (int r = 0; r < 8; r++) { acc01[r] = zz; acc23[r] = zz; }

    for (int kk = 0; kk < HID; kk += 64) {
#pragma unroll
        for (int i = tid; i < 1024; i += 256) {
            int ar = i >> 4, ac4 = i & 15;
            int grow = rowBase + ar;
            float4 v = make_float4(0.0f, 0.0f, 0.0f, 0.0f);
            if (grow < N_NODES)
                v = __ldg((const float4 *)(A + (size_t)grow * HID + kk) + ac4);
            if (apply_bn) {
                int c = kk + ac4 * 4;
                v.x = fmaxf(v.x * g_scale[c + 0] + g_shift[c + 0], 0.0f);
                v.y = fmaxf(v.y * g_scale[c + 1] + g_shift[c + 1], 0.0f);
                v.z = fmaxf(v.z * g_scale[c + 2] + g_shift[c + 2], 0.0f);
                v.w = fmaxf(v.w * g_scale[c + 3] + g_shift[c + 3], 0.0f);
            }
            *(float4 *)&Ash[ar * 64 + ac4 * 4] = v;
        }
#pragma unroll
        for (int i = tid; i < 2048; i += 256) {
            int wr = i >> 5, wc4 = i & 31;
            *(float4 *)&Wsh[wr * 128 + wc4 * 4] =
                __ldg((const float4 *)(W + (size_t)(kk + wr) * HID) + wc4);
        }
        __syncthreads();
#pragma unroll 4
        for (int k4 = 0; k4 < 64; k4 += 4) {
            float4 av[8];
#pragma unroll
            for (int r = 0; r < 8; r++)
                av[r] = *(const float4 *)&Ash[(ty * 8 + r) * 64 + k4];
#pragma unroll
            for (int k2 = 0; k2 < 4; k2++) {
                float4 w = *(const float4 *)&Wsh[(k4 + k2) * 128 + tx * 4];
                unsigned long long w01 = pack2(w.x, w.y);
                unsigned long long w23 = pack2(w.z, w.w);
#pragma unroll
                for (int r = 0; r < 8; r++) {
                    float a = (k2 == 0) ? av[r].x : (k2 == 1) ? av[r].y
                              : (k2 == 2) ? av[r].z : av[r].w;
                    unsigned long long aa = pack2(a, a);
                    acc01[r] = ffma2(aa, w01, acc01[r]);
                    acc23[r] = ffma2(aa, w23, acc23[r]);
                }
            }
        }
        __syncthreads();
    }

    int c0 = tx * 4;
    float b0 = __ldg(bias + c0 + 0), b1 = __ldg(bias + c0 + 1);
    float b2 = __ldg(bias + c0 + 2), b3 = __ldg(bias + c0 + 3);
    float s0 = 0, s1 = 0, s2 = 0, s3 = 0;
    float q0 = 0, q1 = 0, q2 = 0, q3 = 0;
#pragma unroll
    for (int r = 0; r < 8; r++) {
        int grow = rowBase + ty * 8 + r;
        if (grow < N_NODES) {
            float y0, y1, y2, y3;
            unpack2(acc01[r], y0, y1);
            unpack2(acc23[r], y2, y3);
            y0 += b0; y1 += b1; y2 += b2; y3 += b3;
            if (relu_out) {
                y0 = fmaxf(y0, 0.0f); y1 = fmaxf(y1, 0.0f);
                y2 = fmaxf(y2, 0.0f); y3 = fmaxf(y3, 0.0f);
            }
            *(float4 *)(out + (size_t)grow * ostride + ocol + c0) =
                make_float4(y0, y1, y2, y3);
            if (do_stats) {
                s0 += y0; s1 += y1; s2 += y2; s3 += y3;
                q0 += y0 * y0; q1 += y1 * y1; q2 += y2 * y2; q3 += y3 * y3;
            }
        }
    }
    if (do_stats) {
        float *sred = Ash;
        sred[tid] = 0.0f;
        __syncthreads();
        atomicAdd(&sred[c0 + 0], s0); atomicAdd(&sred[c0 + 1], s1);
        atomicAdd(&sred[c0 + 2], s2); atomicAdd(&sred[c0 + 3], s3);
        atomicAdd(&sred[128 + c0 + 0], q0); atomicAdd(&sred[128 + c0 + 1], q1);
        atomicAdd(&sred[128 + c0 + 2], q2); atomicAdd(&sred[128 + c0 + 3], q3);
        __syncthreads();
        atomicAdd(&g_stats[tid], sred[tid]);
    }
}

__global__ void bn_finalize_kernel(const float *__restrict__ gamma,
                                   const float *__restrict__ beta) {
    int c = threadIdx.x;  // 128 threads
    float inv = 1.0f / (float)N_NODES;
    float mu = g_stats[c] * inv;
    float var = g_stats[HID + c] * inv - mu * mu;
    float rs = rsqrtf(var + BN_EPS);
    float sc = rs * __ldg(gamma + c);
    g_scale[c] = sc;
    g_shift[c] = __ldg(beta + c) - mu * sc;
}

// ---------------- readout: graph_ids is SORTED -> contiguous segments ----------------
static __device__ __forceinline__ int lower_bound_dev(const int *a, int n, int key) {
    int lo = 0, hi = n;
    while (lo < hi) {
        int mid = (lo + hi) >> 1;
        if (__ldg(a + mid) < key) lo = mid + 1; else hi = mid;
    }
    return lo;
}

__global__ void readout_kernel(const int *__restrict__ gid) {
    __shared__ int s_rng[2];
    int g = blockIdx.x, t = threadIdx.x;  // 256 blocks x 256 threads
    if (t < 2) s_rng[t] = lower_bound_dev(gid, N_NODES, g + t);
    __syncthreads();
    int beg = s_rng[0], end = s_rng[1];
    float acc = 0.0f;
    for (int n = beg; n < end; n++)
        acc += __ldg(g_hcat + (size_t)n * (2 * HID) + t);
    g_hg[(size_t)g * (2 * HID) + t] = acc;
}

// ---------------- tiny MLP head ----------------
__global__ void mlp_kernel(const float *__restrict__ X, int K,
                           const float *__restrict__ W,
                           const float *__restrict__ b,
                           float *__restrict__ Y, int relu) {
    __shared__ float row[256];
    int g = blockIdx.x, t = threadIdx.x;  // 128 threads
    for (int k = t; k < K; k += 128) row[k] = __ldg(X + (size_t)g * K + k);
    __syncthreads();
    float acc = 0.0f;
#pragma unroll 8
    for (int k = 0; k < K; k++) acc = fmaf(row[k], __ldg(W + (size_t)k * HID + t), acc);
    acc += __ldg(b + t);
    if (relu) acc = fmaxf(acc, 0.0f);
    Y[(size_t)g * HID + t] = acc;
}

__global__ void mlp_out_kernel(const float *__restrict__ W3,
                               const float *__restrict__ b3,
                               float *__restrict__ out) {
    __shared__ float w[HID];
    int t = threadIdx.x;  // 256 threads
    if (t < HID) w[t] = __ldg(W3 + t);
    __syncthreads();
    float acc = 0.0f;
#pragma unroll 8
    for (int k = 0; k < HID; k++) acc = fmaf(g_m2[(size_t)t * HID + k], w[k], acc);
    out[t] = acc + __ldg(b3);
}

// ---------------- launch ----------------
extern "C" void kernel_launch(void *const *d_in, const int *in_sizes, int n_in,
                              void *d_out, int out_size) {
    const float *feats = (const float *)d_in[0];
    const int *src = (const int *)d_in[1];
    const int *dst = (const int *)d_in[2];
    const int *gid = (const int *)d_in[3];
    int base = (in_sizes[4] == 4) ? 4 : 5;  // d_in[4] = scalar n_graphs or eps
    const float *eps = (const float *)d_in[base + 0];
    const float *Wa  = (const float *)d_in[base + 1];
    const float *ba  = (const float *)d_in[base + 2];
    const float *bng = (const float *)d_in[base + 3];
    const float *bnb = (const float *)d_in[base + 4];
    const float *Wb  = (const float *)d_in[base + 5];
    const float *bb  = (const float *)d_in[base + 6];
    const float *oW1 = (const float *)d_in[base + 7];
    const float *ob1 = (const float *)d_in[base + 8];
    const float *oW2 = (const float *)d_in[base + 9];
    const float *ob2 = (const float *)d_in[base + 10];
    const float *oW3 = (const float *)d_in[base + 11];
    const float *ob3 = (const float *)d_in[base + 12];
    float *out = (float *)d_out;

    void *p;
    cudaGetSymbolAddress(&p, g_agg);   float *agg  = (float *)p;
    cudaGetSymbolAddress(&p, g_x1);    float *x1   = (float *)p;
    cudaGetSymbolAddress(&p, g_h);     float *h    = (float *)p;
    cudaGetSymbolAddress(&p, g_hcat);  float *hcat = (float *)p;
    cudaGetSymbolAddress(&p, g_hg);    float *hg   = (float *)p;
    cudaGetSymbolAddress(&p, g_m1);    float *m1   = (float *)p;
    cudaGetSymbolAddress(&p, g_m2);    float *m2   = (float *)p;
    cudaGetSymbolAddress(&p, g_ptr);   int *ptr0   = (int *)p;
    cudaGetSymbolAddress(&p, g_cursor);int *cursor = (int *)p;
    cudaGetSymbolAddress(&p, g_csrc);  int *csrc0  = (int *)p;

    const int GEMM_BLOCKS = (N_NODES + 63) / 64;       // 782
    const int EDGE_BLOCKS = N_EDGES / 256;             // 3125 (exact)
    const int GATHER_BLOCKS = N_NODES / 8;             // 6250 (exact)
    const int DEG_BLOCKS = (N_NODES + 255) / 256;      // 196

    // ---- build dst-CSR per edge type (used by both layers) ----
    for (int e = 0; e < 2; e++) {
        int *ptr_e = ptr0 + e * (N_NODES + 1);
        int *csrc_e = csrc0 + e * N_EDGES;
        zero_deg_kernel<<<DEG_BLOCKS, 256>>>();
        hist_kernel<<<EDGE_BLOCKS, 256>>>(dst + e * N_EDGES);
        scan_kernel<<<1, 1024>>>(ptr_e, cursor);
        reorder_kernel<<<EDGE_BLOCKS, 256>>>(src + e * N_EDGES, dst + e * N_EDGES,
                                             csrc_e);
    }

    for (int e = 0; e < 2; e++) {
        int *ptr_e = ptr0 + e * (N_NODES + 1);
        int *csrc_e = csrc0 + e * N_EDGES;
        const float *hin = feats;
        for (int l = 0; l < 2; l++) {
            int idx = e * 2 + l;
            gather_agg_kernel<<<GATHER_BLOCKS, 256>>>(hin, ptr_e, csrc_e, eps, idx);
            gemm_kernel<<<GEMM_BLOCKS, 256>>>(agg, Wa + (size_t)idx * HID * HID,
                                              ba + idx * HID, x1, HID, 0,
                                              /*bn*/0, /*relu*/0, /*stats*/1);
            bn_finalize_kernel<<<1, HID>>>(bng + idx * HID, bnb + idx * HID);
            if (l == 0) {
                gemm_kernel<<<GEMM_BLOCKS, 256>>>(x1, Wb + (size_t)idx * HID * HID,
                                                  bb + idx * HID, h, HID, 0,
                                                  /*bn*/1, /*relu*/1, /*stats*/0);
            } else {
                gemm_kernel<<<GEMM_BLOCKS, 256>>>(x1, Wb + (size_t)idx * HID * HID,
                                                  bb + idx * HID, hcat, 2 * HID,
                                                  e * HID,
                                                  /*bn*/1, /*relu*/0, /*stats*/0);
            }
            hin = h;
        }
    }

    readout_kernel<<<N_GRAPHS, 2 * HID>>>(gid);
    mlp_kernel<<<N_GRAPHS, HID>>>(hg, 2 * HID, oW1, ob1, m1, 1);
    mlp_kernel<<<N_GRAPHS, HID>>>(m1, HID, oW2, ob2, m2, 1);
    mlp_out_kernel<<<1, N_GRAPHS>>>(oW3, ob3, out);
}